// round 14
// baseline (speedup 1.0000x reference)
#include <cuda_runtime.h>

// HopfieldNetwork: B=8, N=4096, ITERS=10 asynchronous sweeps.
// R14 = R13 (1267us) with TPB 512->1024 (ZPT 8->4): 8 warps/SMSP. Per-warp
// issue work halves again (axpy 4 IMAD.WIDE, candgen ~20 instr, spec row =
// one LDG.128/thread); the fixed per-round chain (BAR/LDS/REDUX) is
// unchanged. Same single-flip rounds, static per-sweep candidate keys,
// register spec row (2nd candidate), L1 prefetch (3rd candidate).
// z int64 scale 2^40; wq = rn(W*2^40); flip delta = +-2*wq via IMAD.WIDE.

constexpr int NN  = 4096;
constexpr int TPB = 1024;
constexpr int ZPT = 4;
constexpr int INF = 0x7FFFFFFF;

__device__ long long g_z[8 * NN];                      // z, int64, scale 2^40
__device__ __align__(16) int g_Wq[NN * NN];            // rn(W * 2^40)
__device__ __align__(16) unsigned char g_xsign[NN];    // bit b = (x[b][c] < 0)

// ---------------------------------------------------------------------------
__global__ void __launch_bounds__(256) prep_wq(const float* __restrict__ W,
                                               const float* __restrict__ x,
                                               int B)
{
    const int base = (blockIdx.x * 256 + threadIdx.x) * 16;
    const float4* w4 = reinterpret_cast<const float4*>(W + base);
    int4* o4 = reinterpret_cast<int4*>(g_Wq + base);
#pragma unroll
    for (int g = 0; g < 4; g++) {
        const float4 v = w4[g];
        int4 o;
        o.x = __float2int_rn(v.x * 0x1.0p40f);
        o.y = __float2int_rn(v.y * 0x1.0p40f);
        o.z = __float2int_rn(v.z * 0x1.0p40f);
        o.w = __float2int_rn(v.w * 0x1.0p40f);
        o4[g] = o;
    }
    if (blockIdx.x == 0) {
        for (int c = threadIdx.x * 16; c < threadIdx.x * 16 + 16; c++) {
            unsigned v = 0;
#pragma unroll
            for (int b = 0; b < 8; b++)
                if (b < B && x[(size_t)b * NN + c] < 0.f) v |= 1u << b;
            g_xsign[c] = (unsigned char)v;
        }
    }
}

// ---------------------------------------------------------------------------
__global__ void __launch_bounds__(256) gemv_init(int B)
{
    const int row  = blockIdx.x;
    const int tid  = threadIdx.x;
    const int base = tid * 16;
    const int lane = tid & 31, wid = tid >> 5;

    const uint4 sb4 = *reinterpret_cast<const uint4*>(g_xsign + base);
    const unsigned sb[4] = {sb4.x, sb4.y, sb4.z, sb4.w};

    const int4* w4 = reinterpret_cast<const int4*>(g_Wq + (size_t)row * NN + base);
    const int4 wa = w4[0], wb = w4[1], wc = w4[2], wd = w4[3];
    const int wq[16] = {wa.x, wa.y, wa.z, wa.w,  wb.x, wb.y, wb.z, wb.w,
                        wc.x, wc.y, wc.z, wc.w,  wd.x, wd.y, wd.z, wd.w};

    long long acc[8];
#pragma unroll
    for (int b = 0; b < 8; b++) acc[b] = 0ll;

#pragma unroll
    for (int k = 0; k < 16; k++) {
        const unsigned byte = (sb[k >> 2] >> (8 * (k & 3))) & 0xFFu;
        const int w = wq[k];
#pragma unroll
        for (int b = 0; b < 8; b++) {
            const int yb = 1 - 2 * (int)((byte >> b) & 1u);
            acc[b] += (long long)w * yb;          // IMAD.WIDE
        }
    }

#pragma unroll
    for (int b = 0; b < 8; b++) {
#pragma unroll
        for (int off = 16; off > 0; off >>= 1)
            acc[b] += __shfl_down_sync(0xffffffffu, acc[b], off);
    }
    __shared__ long long red[8][8];
    if (lane == 0) {
#pragma unroll
        for (int b = 0; b < 8; b++) red[wid][b] = acc[b];
    }
    __syncthreads();
    if (tid < 8) {
        long long s = 0ll;
#pragma unroll
        for (int w2 = 0; w2 < 8; w2++) s += red[w2][tid];
        if (tid < B) g_z[tid * NN + row] = s;
    }
}

// ---------------------------------------------------------------------------
// Kernel 2: one block per sample, one barrier per flip.
// Key pack: bits[0]=nb(=!y_sign), [1:13]=neuron i, [13:25]=pos-in-sweep.
// ---------------------------------------------------------------------------
__global__ void __launch_bounds__(TPB, 1) hopfield_seq(
    const float* __restrict__ x,
    const int*   __restrict__ perms,
    float*       __restrict__ out,
    int iters)
{
    const int b    = blockIdx.x;
    const int tid  = threadIdx.x;
    const int lane = tid & 31;
    const int wid  = tid >> 5;          // 32 warps
    const int base = tid * ZPT;

    __shared__ __align__(16) unsigned short pos_of[NN];   // neuron -> pos
    __shared__ __align__(16) int sh_slot[2][32];

    // ---- load z slice and x signs into registers ----
    long long z[ZPT];
    {
        const long long* gz = g_z + (size_t)b * NN + base;
#pragma unroll
        for (int k = 0; k < ZPT; k++) z[k] = gz[k];
    }

    unsigned ym = 0;   // bit k = (y[base+k] < 0)
    {
        const float4 xv = *reinterpret_cast<const float4*>(x + (size_t)b * NN + base);
        ym |= (__float_as_uint(xv.x) >> 31) << 0;
        ym |= (__float_as_uint(xv.y) >> 31) << 1;
        ym |= (__float_as_uint(xv.z) >> 31) << 2;
        ym |= (__float_as_uint(xv.w) >> 31) << 3;
    }

    const int* pb = perms + (size_t)b * iters * NN;
    int parity  = 0;
    int spec_id = -1;          // neuron whose Wq row sits in specv
    int specv[ZPT];
#pragma unroll
    for (int k = 0; k < ZPT; k++) specv[k] = 0;

    for (int sweep = 0; sweep < iters; sweep++) {
        // ---- build neuron -> position table for this sweep ----
        const int* ps = pb + sweep * NN;
        {
            const int4 a = *reinterpret_cast<const int4*>(ps + tid * 4);
            const int p0 = tid * 4;
            pos_of[a.x] = (unsigned short)(p0 + 0);
            pos_of[a.y] = (unsigned short)(p0 + 1);
            pos_of[a.z] = (unsigned short)(p0 + 2);
            pos_of[a.w] = (unsigned short)(p0 + 3);
        }
        __syncthreads();                         // pos_of visible

        // ---- static per-sweep candidate keys + sign-xor masks ----
        int ckey[ZPT];      // (pos<<13)|(neuron<<1)|(!y_sign)
        int zmask[ZPT];     // y_sign << 31
#pragma unroll
        for (int k = 0; k < ZPT; k++) {
            const int yb = (int)((ym >> k) & 1u);
            ckey[k]  = ((int)pos_of[base + k] << 13) | ((base + k) << 1) | (yb ^ 1);
            zmask[k] = yb << 31;
        }

        int thr = -1;

        // ---- initial candidates for this sweep ----
        {
            unsigned key = (unsigned)INF;
#pragma unroll
            for (int k = 0; k < ZPT; k++) {
                const int t = (int)(z[k] >> 32) ^ zmask[k];
                if (t < 0) key = min(key, (unsigned)ckey[k]);
            }
            const unsigned wmin = __reduce_min_sync(0xffffffffu, key);
            if (lane == 0) sh_slot[parity][wid] = (int)wmin;
        }
        __syncthreads();                         // slots visible

        // ---- flip rounds: one barrier each ----
        for (;;) {
            // lane-parallel decode: one slot per lane, redux for top-3
            const int a  = sh_slot[parity][lane];
            parity ^= 1;
            const int mk = (int)__reduce_min_sync(0xffffffffu, (unsigned)a);
            if (mk == INF) break;                // sweep finished

            const int e  = (a == mk) ? INF : a;
            const int r2 = (int)__reduce_min_sync(0xffffffffu, (unsigned)e);

            const int fi = (mk >> 1) & 0xFFF;
            const int nb = mk & 1;
            thr = mk;

            // flip delta is +-2*W at scale 2^40 -> add +-2*wq
            const int sfd = 2 - 4 * nb;

            // ---- axpy: one IMAD.WIDE per element ----
            if (fi == spec_id) {                 // uniform branch: spec hit
#pragma unroll
                for (int k = 0; k < ZPT; k++)
                    z[k] += (long long)specv[k] * sfd;
            } else {                             // miss: demand load
                const int4 da = __ldg(
                    reinterpret_cast<const int4*>(g_Wq + (size_t)fi * NN + base));
                const int dv[ZPT] = {da.x, da.y, da.z, da.w};
#pragma unroll
                for (int k = 0; k < ZPT; k++)
                    z[k] += (long long)dv[k] * sfd;
            }

            // ---- speculative register load of 2nd candidate's row ----
            const int nsid = (r2 != INF) ? ((r2 >> 1) & 0xFFF) : -1;
            if (nsid >= 0) {                     // uniform branch
                const int4 sa = __ldg(
                    reinterpret_cast<const int4*>(g_Wq + (size_t)nsid * NN + base));
                specv[0] = sa.x; specv[1] = sa.y; specv[2] = sa.z; specv[3] = sa.w;
            }
            spec_id = nsid;

            // ---- L1 prefetch of 3rd candidate's row (off critical path) ----
            {
                const int e3 = (a == mk || a == r2) ? INF : a;
                const int r3 = (int)__reduce_min_sync(0xffffffffu, (unsigned)e3);
                if (r3 != INF) {
                    const char* p3 = reinterpret_cast<const char*>(
                        g_Wq + (size_t)((r3 >> 1) & 0xFFF) * NN + base);
                    asm volatile("prefetch.global.L1 [%0];" :: "l"(p3));
                }
            }

            // owner records the flip in its y bits (stale ckey/zmask excluded
            // by ckey > thr for the rest of the sweep)
            if (tid == (fi >> 2)) ym ^= 1u << (fi & 3);

            // ---- candidate regeneration: static keys, sign-xor test ----
            {
                unsigned key = (unsigned)INF;
#pragma unroll
                for (int k = 0; k < ZPT; k++) {
                    const int t = (int)(z[k] >> 32) ^ zmask[k];
                    if (t < 0 && ckey[k] > thr) key = min(key, (unsigned)ckey[k]);
                }
                const unsigned wmin = __reduce_min_sync(0xffffffffu, key);
                if (lane == 0) sh_slot[parity][wid] = (int)wmin;
            }
            __syncthreads();                     // the single barrier
        }
    }

    // ---- write y from register state ----
    float4 o;
    o.x = ((ym >> 0) & 1u) ? -1.0f : 1.0f;
    o.y = ((ym >> 1) & 1u) ? -1.0f : 1.0f;
    o.z = ((ym >> 2) & 1u) ? -1.0f : 1.0f;
    o.w = ((ym >> 3) & 1u) ? -1.0f : 1.0f;
    *reinterpret_cast<float4*>(out + (size_t)b * NN + base) = o;
}

// ---------------------------------------------------------------------------
extern "C" void kernel_launch(void* const* d_in, const int* in_sizes, int n_in,
                              void* d_out, int out_size)
{
    const float* x     = (const float*)d_in[0];
    const float* W     = (const float*)d_in[1];
    const int*   perms = (const int*)  d_in[2];
    float*       out   = (float*)d_out;

    const int B     = in_sizes[0] / NN;
    const int iters = in_sizes[2] / in_sizes[0];

    prep_wq<<<NN * NN / (256 * 16), 256>>>(W, x, B);
    gemv_init<<<NN, 256>>>(B);
    hopfield_seq<<<B, TPB>>>(x, perms, out, iters);
}